// round 2
// baseline (speedup 1.0000x reference)
#include <cuda_runtime.h>
#include <cstdint>

#define Ncfg 8192
#define Ecfg 524288

// ---------------- device scratch (static; no runtime allocation) ----------------
__device__ int   g_deg[2][Ncfg];
__device__ float g_dinv[2][Ncfg];
__device__ int   g_rowptr[2][Ncfg + 1];
__device__ int   g_cursor[2][Ncfg];
__device__ int   g_col[2][Ecfg];

__device__ float g_T  [2 * Ncfg * 64];   // Agg(X)
__device__ float g_H1 [2 * Ncfg * 128];  // relu(T@W1+b1)
__device__ float g_G2 [2 * Ncfg * 64];   // H1@W2
__device__ float g_H2 [2 * Ncfg * 64];   // relu(Agg(G2)+b2)
__device__ float g_G3 [2 * Ncfg * 32];   // H2@W3
__device__ float g_Emb[2 * Ncfg * 32];   // Agg(G3)+b3
__device__ float g_m[2][32];             // matching vectors

// Buffer selectors (avoid any host-side symbol-address API)
#define BUF_T   0
#define BUF_H1  1
#define BUF_G2  2
#define BUF_H2  3
#define BUF_G3  4
#define BUF_EMB 5

__device__ __forceinline__ float* devbuf(int sel) {
    switch (sel) {
        case BUF_T:  return g_T;
        case BUF_H1: return g_H1;
        case BUF_G2: return g_G2;
        case BUF_H2: return g_H2;
        case BUF_G3: return g_G3;
        default:     return g_Emb;
    }
}

__device__ __forceinline__ unsigned long long ffma2(unsigned long long a,
                                                    unsigned long long b,
                                                    unsigned long long c) {
    unsigned long long d;
    asm("fma.rn.f32x2 %0, %1, %2, %3;" : "=l"(d) : "l"(a), "l"(b), "l"(c));
    return d;
}

// ---------------- CSR build ----------------
__global__ void zero_deg_kernel() {
    int i = blockIdx.x * blockDim.x + threadIdx.x;
    if (i < 2 * Ncfg) ((int*)g_deg)[i] = 0;
}

__global__ void count_kernel(const int* __restrict__ e0, const int* __restrict__ e1) {
    int g = blockIdx.y;
    const int* e = g ? e1 : e0;
    int i = blockIdx.x * blockDim.x + threadIdx.x;
    if (i < Ecfg) atomicAdd(&g_deg[g][e[Ecfg + i]], 1);
}

__global__ void scan_kernel() {
    int g = blockIdx.x;
    int tid = threadIdx.x;
    int v[8];
    int tot = 0;
#pragma unroll
    for (int i = 0; i < 8; i++) { v[i] = g_deg[g][tid * 8 + i]; tot += v[i]; }
    __shared__ int s[1024];
    s[tid] = tot;
    __syncthreads();
    for (int off = 1; off < 1024; off <<= 1) {
        int t = (tid >= off) ? s[tid - off] : 0;
        __syncthreads();
        s[tid] += t;
        __syncthreads();
    }
    int run = s[tid] - tot;  // exclusive base
#pragma unroll
    for (int i = 0; i < 8; i++) {
        int idx = tid * 8 + i;
        g_rowptr[g][idx] = run;
        g_cursor[g][idx] = run;
        g_dinv[g][idx] = rsqrtf((float)(v[i] + 1));  // +1 self loop
        run += v[i];
    }
    if (tid == 1023) g_rowptr[g][Ncfg] = run;
}

__global__ void fill_kernel(const int* __restrict__ e0, const int* __restrict__ e1) {
    int g = blockIdx.y;
    const int* e = g ? e1 : e0;
    int i = blockIdx.x * blockDim.x + threadIdx.x;
    if (i < Ecfg) {
        int d = e[Ecfg + i];
        int p = atomicAdd(&g_cursor[g][d], 1);
        g_col[g][p] = e[i];
    }
}

// ---------------- aggregation ----------------
// out[d] = dinv[d]*( sum_{s->d} dinv[s]*P[s] + dinv[d]*P[d] ) (+bias)(relu)
// EPI: 0 = none, 1 = bias+relu, 2 = bias. EXT_IN: input comes from kernel params.
template <int F, int EPI, bool EXT_IN>
__global__ void agg_kernel(const float* __restrict__ X0, const float* __restrict__ X1,
                           int inSel, int outSel, const float* __restrict__ bias) {
    int g = blockIdx.y;
    const float* __restrict__ P =
        EXT_IN ? (g ? X1 : X0) : (devbuf(inSel) + (size_t)g * Ncfg * F);
    float* __restrict__ O = devbuf(outSel) + (size_t)g * Ncfg * F;
    const float* __restrict__ dinv = g_dinv[g];
    const int* __restrict__ col = g_col[g];

    int warp = (blockIdx.x * blockDim.x + threadIdx.x) >> 5;
    int lane = threadIdx.x & 31;
    if (warp >= Ncfg) return;
    int d = warp;
    int beg = g_rowptr[g][d];
    int end = g_rowptr[g][d + 1];
    float wd = dinv[d];

    if (F == 64) {
        float2 pv = ((const float2*)(P + (size_t)d * 64))[lane];
        float ax = wd * pv.x, ay = wd * pv.y;
        int j = beg;
        for (; j + 4 <= end; j += 4) {
            int s0 = col[j], s1 = col[j + 1], s2 = col[j + 2], s3 = col[j + 3];
            float w0 = dinv[s0], w1 = dinv[s1], w2 = dinv[s2], w3 = dinv[s3];
            float2 v0 = ((const float2*)(P + (size_t)s0 * 64))[lane];
            float2 v1 = ((const float2*)(P + (size_t)s1 * 64))[lane];
            float2 v2 = ((const float2*)(P + (size_t)s2 * 64))[lane];
            float2 v3 = ((const float2*)(P + (size_t)s3 * 64))[lane];
            ax += w0 * v0.x; ay += w0 * v0.y;
            ax += w1 * v1.x; ay += w1 * v1.y;
            ax += w2 * v2.x; ay += w2 * v2.y;
            ax += w3 * v3.x; ay += w3 * v3.y;
        }
        for (; j < end; ++j) {
            int s = col[j];
            float w = dinv[s];
            float2 v = ((const float2*)(P + (size_t)s * 64))[lane];
            ax += w * v.x; ay += w * v.y;
        }
        ax *= wd; ay *= wd;
        if (EPI >= 1) {
            ax += bias[2 * lane];
            ay += bias[2 * lane + 1];
            if (EPI == 1) { ax = fmaxf(ax, 0.f); ay = fmaxf(ay, 0.f); }
        }
        ((float2*)(O + (size_t)d * 64))[lane] = make_float2(ax, ay);
    } else {  // F == 32
        float a = wd * P[(size_t)d * 32 + lane];
        int j = beg;
        for (; j + 4 <= end; j += 4) {
            int s0 = col[j], s1 = col[j + 1], s2 = col[j + 2], s3 = col[j + 3];
            float w0 = dinv[s0], w1 = dinv[s1], w2 = dinv[s2], w3 = dinv[s3];
            float v0 = P[(size_t)s0 * 32 + lane];
            float v1 = P[(size_t)s1 * 32 + lane];
            float v2 = P[(size_t)s2 * 32 + lane];
            float v3 = P[(size_t)s3 * 32 + lane];
            a += w0 * v0; a += w1 * v1; a += w2 * v2; a += w3 * v3;
        }
        for (; j < end; ++j) {
            int s = col[j];
            a += dinv[s] * P[(size_t)s * 32 + lane];
        }
        a *= wd;
        if (EPI >= 1) {
            a += bias[lane];
            if (EPI == 1) a = fmaxf(a, 0.f);
        }
        O[(size_t)d * 32 + lane] = a;
    }
}

// ---------------- small dense GEMM: O = X[NxK] @ W[KxNOUT] (+bias, relu) ----------------
template <int K, int NOUT, bool BR>
__global__ void gemm_kernel(int inSel, int outSel,
                            const float* __restrict__ W, const float* __restrict__ bias) {
    constexpr int CG = NOUT / 8;      // column groups of 8
    constexpr int ROWS = 256 / CG;    // rows per block
    int g = blockIdx.y;
    const float* __restrict__ X = devbuf(inSel) + (size_t)g * Ncfg * K;
    float* __restrict__ O = devbuf(outSel) + (size_t)g * Ncfg * NOUT;

    __shared__ float Ws[K * NOUT];
    __shared__ float Xs[ROWS * K];
    int tid = threadIdx.x;
    for (int i = tid; i < K * NOUT; i += 256) Ws[i] = W[i];
    int row0 = blockIdx.x * ROWS;
    for (int i = tid; i < ROWS * K; i += 256) Xs[i] = X[(size_t)row0 * K + i];
    __syncthreads();

    int cgi = tid % CG;
    int r = tid / CG;
    int c0 = cgi * 8;
    float acc[8];
#pragma unroll
    for (int i = 0; i < 8; i++) acc[i] = BR ? bias[c0 + i] : 0.f;

#pragma unroll 4
    for (int k = 0; k < K; k++) {
        float x = Xs[r * K + k];
        float4 w0 = *(const float4*)&Ws[k * NOUT + c0];
        float4 w1 = *(const float4*)&Ws[k * NOUT + c0 + 4];
        acc[0] += x * w0.x; acc[1] += x * w0.y; acc[2] += x * w0.z; acc[3] += x * w0.w;
        acc[4] += x * w1.x; acc[5] += x * w1.y; acc[6] += x * w1.z; acc[7] += x * w1.w;
    }
    if (BR) {
#pragma unroll
        for (int i = 0; i < 8; i++) acc[i] = fmaxf(acc[i], 0.f);
    }
    size_t off = (size_t)(row0 + r) * NOUT + c0;
    *(float4*)&O[off]     = make_float4(acc[0], acc[1], acc[2], acc[3]);
    *(float4*)&O[off + 4] = make_float4(acc[4], acc[5], acc[6], acc[7]);
}

// ---------------- matching: m[g] = tanh( colsum(Emb_g) @ M_g ) ----------------
__global__ void match_kernel(const float* __restrict__ M1, const float* __restrict__ M2) {
    int g = blockIdx.x;
    const float* __restrict__ Emb = g_Emb + (size_t)g * Ncfg * 32;
    const float* __restrict__ M = g ? M2 : M1;
    int tid = threadIdx.x;
    int col = tid & 31;
    int seg = tid >> 5;  // 8 segments of 1024 rows
    float p = 0.f;
    int rbeg = seg * 1024;
    for (int r = rbeg; r < rbeg + 1024; r++) p += Emb[(size_t)r * 32 + col];
    __shared__ float red[256];
    red[tid] = p;
    __syncthreads();
    for (int st = 128; st >= 32; st >>= 1) {
        if (tid < st) red[tid] += red[tid + st];
        __syncthreads();
    }
    if (tid < 32) {
        float mm = 0.f;
#pragma unroll
        for (int k = 0; k < 32; k++) mm += red[k] * M[k * 32 + tid];
        g_m[g][tid] = tanhf(mm);
    }
}

// ---------------- final: out = sigmoid( (f1 - m2) @ (f2 - m1)^T ) ----------------
__global__ __launch_bounds__(256, 2) void final_kernel(float* __restrict__ out) {
    __shared__ float2 As2[32 * 128];  // k-major, a duplicated into both halves
    __shared__ float  Bs[32 * 128];   // k-major
    const float* __restrict__ Emb1 = g_Emb;                          // f1
    const float* __restrict__ Emb2 = g_Emb + (size_t)Ncfg * 32;      // f2
    int tid = threadIdx.x;
    int row0 = blockIdx.y * 128;
    int col0 = blockIdx.x * 128;

#pragma unroll
    for (int t = 0; t < 4; t++) {
        int g4 = t * 256 + tid;        // 0..1023
        int r = g4 >> 3;               // 0..127
        int k4 = (g4 & 7) * 4;         // 0..28 step 4
        float4 v = *(const float4*)&Emb1[(size_t)(row0 + r) * 32 + k4];
        float a0 = v.x - g_m[1][k4 + 0];
        float a1 = v.y - g_m[1][k4 + 1];
        float a2 = v.z - g_m[1][k4 + 2];
        float a3 = v.w - g_m[1][k4 + 3];
        As2[(k4 + 0) * 128 + r] = make_float2(a0, a0);
        As2[(k4 + 1) * 128 + r] = make_float2(a1, a1);
        As2[(k4 + 2) * 128 + r] = make_float2(a2, a2);
        As2[(k4 + 3) * 128 + r] = make_float2(a3, a3);
        float4 u = *(const float4*)&Emb2[(size_t)(col0 + r) * 32 + k4];
        Bs[(k4 + 0) * 128 + r] = u.x - g_m[0][k4 + 0];
        Bs[(k4 + 1) * 128 + r] = u.y - g_m[0][k4 + 1];
        Bs[(k4 + 2) * 128 + r] = u.z - g_m[0][k4 + 2];
        Bs[(k4 + 3) * 128 + r] = u.w - g_m[0][k4 + 3];
    }
    __syncthreads();

    int tx = tid & 15, ty = tid >> 4;
    int r0 = ty * 8, c0 = tx * 8;
    unsigned long long acc[8][4];
#pragma unroll
    for (int i = 0; i < 8; i++)
#pragma unroll
        for (int j = 0; j < 4; j++) acc[i][j] = 0ULL;

#pragma unroll 4
    for (int k = 0; k < 32; k++) {
        const unsigned long long* ap = (const unsigned long long*)(As2 + k * 128 + r0);
        const unsigned long long* bp = (const unsigned long long*)(Bs + k * 128 + c0);
        unsigned long long a_[8], b_[4];
#pragma unroll
        for (int i = 0; i < 8; i++) a_[i] = ap[i];
#pragma unroll
        for (int j = 0; j < 4; j++) b_[j] = bp[j];
#pragma unroll
        for (int i = 0; i < 8; i++)
#pragma unroll
            for (int j = 0; j < 4; j++) acc[i][j] = ffma2(a_[i], b_[j], acc[i][j]);
    }

#pragma unroll
    for (int i = 0; i < 8; i++) {
        float o[8];
#pragma unroll
        for (int j = 0; j < 4; j++) {
            unsigned long long v = acc[i][j];
            o[2 * j]     = __uint_as_float((unsigned)(v & 0xffffffffu));
            o[2 * j + 1] = __uint_as_float((unsigned)(v >> 32));
        }
#pragma unroll
        for (int j = 0; j < 8; j++) {
            float e = __expf(-o[j]);
            o[j] = __fdividef(1.f, 1.f + e);
        }
        size_t off = (size_t)(row0 + r0 + i) * Ncfg + (col0 + c0);
        *(float4*)&out[off]     = make_float4(o[0], o[1], o[2], o[3]);
        *(float4*)&out[off + 4] = make_float4(o[4], o[5], o[6], o[7]);
    }
}

// ---------------- launch (pure kernel launches; graph-capture-safe) ----------------
extern "C" void kernel_launch(void* const* d_in, const int* in_sizes, int n_in,
                              void* d_out, int out_size) {
    (void)in_sizes; (void)n_in; (void)out_size;
    const int*   e1 = (const int*)d_in[0];
    const int*   e2 = (const int*)d_in[1];
    const float* x1 = (const float*)d_in[2];
    const float* x2 = (const float*)d_in[3];
    const float* W1 = (const float*)d_in[4];
    const float* b1 = (const float*)d_in[5];
    const float* W2 = (const float*)d_in[6];
    const float* b2 = (const float*)d_in[7];
    const float* W3 = (const float*)d_in[8];
    const float* b3 = (const float*)d_in[9];
    const float* M1 = (const float*)d_in[10];
    const float* M2 = (const float*)d_in[11];
    float* out = (float*)d_out;

    // CSR build (both graphs)
    zero_deg_kernel<<<16, 1024>>>();
    count_kernel<<<dim3(Ecfg / 256, 2), 256>>>(e1, e2);
    scan_kernel<<<2, 1024>>>();
    fill_kernel<<<dim3(Ecfg / 256, 2), 256>>>(e1, e2);

    // Layer 1: T = Agg(X);  H1 = relu(T@W1 + b1)
    agg_kernel<64, 0, true><<<dim3(Ncfg / 8, 2), 256>>>(x1, x2, 0, BUF_T, nullptr);
    gemm_kernel<64, 128, true><<<dim3(Ncfg / 16, 2), 256>>>(BUF_T, BUF_H1, W1, b1);

    // Layer 2: G2 = H1@W2;  H2 = relu(Agg(G2) + b2)
    gemm_kernel<128, 64, false><<<dim3(Ncfg / 32, 2), 256>>>(BUF_H1, BUF_G2, W2, nullptr);
    agg_kernel<64, 1, false><<<dim3(Ncfg / 8, 2), 256>>>(nullptr, nullptr, BUF_G2, BUF_H2, b2);

    // Layer 3: G3 = H2@W3;  Emb = Agg(G3) + b3
    gemm_kernel<64, 32, false><<<dim3(Ncfg / 64, 2), 256>>>(BUF_H2, BUF_G3, W3, nullptr);
    agg_kernel<32, 2, false><<<dim3(Ncfg / 8, 2), 256>>>(nullptr, nullptr, BUF_G3, BUF_EMB, b3);

    // Matching vectors
    match_kernel<<<2, 256>>>(M1, M2);

    // Final scores
    final_kernel<<<dim3(Ncfg / 128, Ncfg / 128), 256>>>(out);
}

// round 4
// speedup vs baseline: 1.3123x; 1.3123x over previous
#include <cuda_runtime.h>
#include <cuda_bf16.h>
#include <cstdint>

#define Ncfg 8192
#define Ecfg 524288

// ---------------- device scratch (static; no runtime allocation) ----------------
__device__ int   g_deg[2][Ncfg];
__device__ float g_dinv[2][Ncfg];
__device__ int   g_rowptr[2][Ncfg + 1];
__device__ int   g_cursor[2][Ncfg];
__device__ int   g_col[2][Ecfg];

__device__ float g_T  [2 * Ncfg * 64];   // Agg(X)
__device__ float g_H1 [2 * Ncfg * 128];  // relu(T@W1+b1)
__device__ float g_G2 [2 * Ncfg * 64];   // H1@W2
__device__ float g_H2 [2 * Ncfg * 64];   // relu(Agg(G2)+b2)
__device__ float g_G3 [2 * Ncfg * 32];   // H2@W3
__device__ float g_Emb[2 * Ncfg * 32];   // Agg(G3)+b3
__device__ float g_m[2][32];             // matching vectors
__device__ float g_colsum[2][32];        // column sums of Emb

// bf16-split operands for the final HMMA GEMM (rows of 96 bf16):
// A row: [hi | lo | hi],  B row: [hi | hi | lo]  =>  hiA*hiB + loA*hiB + hiA*loB
__device__ __nv_bfloat16 g_Abf[(size_t)Ncfg * 96];
__device__ __nv_bfloat16 g_Bbf[(size_t)Ncfg * 96];

#define BUF_T   0
#define BUF_H1  1
#define BUF_G2  2
#define BUF_H2  3
#define BUF_G3  4
#define BUF_EMB 5

__device__ __forceinline__ float* devbuf(int sel) {
    switch (sel) {
        case BUF_T:  return g_T;
        case BUF_H1: return g_H1;
        case BUF_G2: return g_G2;
        case BUF_H2: return g_H2;
        case BUF_G3: return g_G3;
        default:     return g_Emb;
    }
}

// ---------------- CSR build ----------------
__global__ void zero_deg_kernel() {
    int i = blockIdx.x * blockDim.x + threadIdx.x;
    if (i < 2 * Ncfg) ((int*)g_deg)[i] = 0;
    if (i < 64) ((float*)g_colsum)[i] = 0.f;
}

// SMEM-privatized histogram: 32 blocks per graph
__global__ void count_kernel(const int* __restrict__ e0, const int* __restrict__ e1) {
    __shared__ int h[Ncfg];
    int g = blockIdx.y;
    const int* __restrict__ dst = (g ? e1 : e0) + Ecfg;
    for (int i = threadIdx.x; i < Ncfg; i += 1024) h[i] = 0;
    __syncthreads();
    int base = blockIdx.x * (Ecfg / 32);
#pragma unroll
    for (int t = 0; t < Ecfg / 32; t += 1024)
        atomicAdd(&h[dst[base + t + threadIdx.x]], 1);
    __syncthreads();
    for (int i = threadIdx.x; i < Ncfg; i += 1024) {
        int v = h[i];
        if (v) atomicAdd(&g_deg[g][i], v);
    }
}

__global__ void scan_kernel() {
    int g = blockIdx.x;
    int tid = threadIdx.x;
    int v[8];
    int tot = 0;
#pragma unroll
    for (int i = 0; i < 8; i++) { v[i] = g_deg[g][tid * 8 + i]; tot += v[i]; }
    __shared__ int s[1024];
    s[tid] = tot;
    __syncthreads();
    for (int off = 1; off < 1024; off <<= 1) {
        int t = (tid >= off) ? s[tid - off] : 0;
        __syncthreads();
        s[tid] += t;
        __syncthreads();
    }
    int run = s[tid] - tot;
#pragma unroll
    for (int i = 0; i < 8; i++) {
        int idx = tid * 8 + i;
        g_rowptr[g][idx] = run;
        g_cursor[g][idx] = run;
        g_dinv[g][idx] = rsqrtf((float)(v[i] + 1));
        run += v[i];
    }
    if (tid == 1023) g_rowptr[g][Ncfg] = run;
}

__global__ void fill_kernel(const int* __restrict__ e0, const int* __restrict__ e1) {
    int g = blockIdx.y;
    const int* e = g ? e1 : e0;
    int i = blockIdx.x * blockDim.x + threadIdx.x;
    if (i < Ecfg) {
        int d = e[Ecfg + i];
        int p = atomicAdd(&g_cursor[g][d], 1);
        g_col[g][p] = e[i];
    }
}

// ---------------- aggregation ----------------
template <int F, int EPI, bool EXT_IN>
__global__ void agg_kernel(const float* __restrict__ X0, const float* __restrict__ X1,
                           int inSel, int outSel, const float* __restrict__ bias) {
    int g = blockIdx.y;
    const float* __restrict__ P =
        EXT_IN ? (g ? X1 : X0) : (devbuf(inSel) + (size_t)g * Ncfg * F);
    float* __restrict__ O = devbuf(outSel) + (size_t)g * Ncfg * F;
    const float* __restrict__ dinv = g_dinv[g];
    const int* __restrict__ col = g_col[g];

    int warp = (blockIdx.x * blockDim.x + threadIdx.x) >> 5;
    int lane = threadIdx.x & 31;
    if (warp >= Ncfg) return;
    int d = warp;
    int beg = g_rowptr[g][d];
    int end = g_rowptr[g][d + 1];
    float wd = dinv[d];

    if (F == 64) {
        float2 pv = ((const float2*)(P + (size_t)d * 64))[lane];
        float ax = wd * pv.x, ay = wd * pv.y;
        int j = beg;
        for (; j + 4 <= end; j += 4) {
            int s0 = col[j], s1 = col[j + 1], s2 = col[j + 2], s3 = col[j + 3];
            float w0 = dinv[s0], w1 = dinv[s1], w2 = dinv[s2], w3 = dinv[s3];
            float2 v0 = ((const float2*)(P + (size_t)s0 * 64))[lane];
            float2 v1 = ((const float2*)(P + (size_t)s1 * 64))[lane];
            float2 v2 = ((const float2*)(P + (size_t)s2 * 64))[lane];
            float2 v3 = ((const float2*)(P + (size_t)s3 * 64))[lane];
            ax += w0 * v0.x; ay += w0 * v0.y;
            ax += w1 * v1.x; ay += w1 * v1.y;
            ax += w2 * v2.x; ay += w2 * v2.y;
            ax += w3 * v3.x; ay += w3 * v3.y;
        }
        for (; j < end; ++j) {
            int s = col[j];
            float w = dinv[s];
            float2 v = ((const float2*)(P + (size_t)s * 64))[lane];
            ax += w * v.x; ay += w * v.y;
        }
        ax *= wd; ay *= wd;
        if (EPI >= 1) {
            ax += bias[2 * lane];
            ay += bias[2 * lane + 1];
            if (EPI == 1) { ax = fmaxf(ax, 0.f); ay = fmaxf(ay, 0.f); }
        }
        ((float2*)(O + (size_t)d * 64))[lane] = make_float2(ax, ay);
    } else {  // F == 32
        float a = wd * P[(size_t)d * 32 + lane];
        int j = beg;
        for (; j + 4 <= end; j += 4) {
            int s0 = col[j], s1 = col[j + 1], s2 = col[j + 2], s3 = col[j + 3];
            float w0 = dinv[s0], w1 = dinv[s1], w2 = dinv[s2], w3 = dinv[s3];
            float v0 = P[(size_t)s0 * 32 + lane];
            float v1 = P[(size_t)s1 * 32 + lane];
            float v2 = P[(size_t)s2 * 32 + lane];
            float v3 = P[(size_t)s3 * 32 + lane];
            a += w0 * v0; a += w1 * v1; a += w2 * v2; a += w3 * v3;
        }
        for (; j < end; ++j) {
            int s = col[j];
            a += dinv[s] * P[(size_t)s * 32 + lane];
        }
        a *= wd;
        if (EPI >= 1) {
            a += bias[lane];
            if (EPI == 1) a = fmaxf(a, 0.f);
        }
        O[(size_t)d * 32 + lane] = a;
    }
}

// ---------------- small dense GEMM: O = X[NxK] @ W[KxNOUT] (+bias, relu) ----------------
template <int K, int NOUT, bool BR>
__global__ void gemm_kernel(int inSel, int outSel,
                            const float* __restrict__ W, const float* __restrict__ bias) {
    constexpr int CG = NOUT / 8;
    constexpr int ROWS = 256 / CG;
    int g = blockIdx.y;
    const float* __restrict__ X = devbuf(inSel) + (size_t)g * Ncfg * K;
    float* __restrict__ O = devbuf(outSel) + (size_t)g * Ncfg * NOUT;

    __shared__ float Ws[K * NOUT];
    __shared__ float Xs[ROWS * K];
    int tid = threadIdx.x;
    for (int i = tid; i < K * NOUT; i += 256) Ws[i] = W[i];
    int row0 = blockIdx.x * ROWS;
    for (int i = tid; i < ROWS * K; i += 256) Xs[i] = X[(size_t)row0 * K + i];
    __syncthreads();

    int cgi = tid % CG;
    int r = tid / CG;
    int c0 = cgi * 8;
    float acc[8];
#pragma unroll
    for (int i = 0; i < 8; i++) acc[i] = BR ? bias[c0 + i] : 0.f;

#pragma unroll 4
    for (int k = 0; k < K; k++) {
        float x = Xs[r * K + k];
        float4 w0 = *(const float4*)&Ws[k * NOUT + c0];
        float4 w1 = *(const float4*)&Ws[k * NOUT + c0 + 4];
        acc[0] += x * w0.x; acc[1] += x * w0.y; acc[2] += x * w0.z; acc[3] += x * w0.w;
        acc[4] += x * w1.x; acc[5] += x * w1.y; acc[6] += x * w1.z; acc[7] += x * w1.w;
    }
    if (BR) {
#pragma unroll
        for (int i = 0; i < 8; i++) acc[i] = fmaxf(acc[i], 0.f);
    }
    size_t off = (size_t)(row0 + r) * NOUT + c0;
    *(float4*)&O[off]     = make_float4(acc[0], acc[1], acc[2], acc[3]);
    *(float4*)&O[off + 4] = make_float4(acc[4], acc[5], acc[6], acc[7]);
}

// ---------------- matching: colsum partials + finish ----------------
__global__ void match_partial_kernel() {
    int g = blockIdx.y;
    const float* __restrict__ Emb = g_Emb + (size_t)g * Ncfg * 32;
    int tid = threadIdx.x;
    int col = tid & 31;
    int seg = tid >> 5;
    int rbeg = blockIdx.x * 128 + seg * 16;
    float p = 0.f;
#pragma unroll
    for (int r = 0; r < 16; r++) p += Emb[(size_t)(rbeg + r) * 32 + col];
    __shared__ float red[256];
    red[tid] = p;
    __syncthreads();
    for (int st = 128; st >= 32; st >>= 1) {
        if (tid < st) red[tid] += red[tid + st];
        __syncthreads();
    }
    if (tid < 32) atomicAdd(&g_colsum[g][tid], red[tid]);
}

__global__ void match_final_kernel(const float* __restrict__ M1, const float* __restrict__ M2) {
    int tid = threadIdx.x;
    int g = tid >> 5, c = tid & 31;
    const float* __restrict__ M = g ? M2 : M1;
    float mm = 0.f;
#pragma unroll
    for (int k = 0; k < 32; k++) mm += g_colsum[g][k] * M[k * 32 + c];
    g_m[g][c] = tanhf(mm);
}

// ---------------- prep: bf16 hi/lo split operands ----------------
__global__ void prep_kernel() {
    int g = blockIdx.y;
    int row = blockIdx.x * 8 + (threadIdx.x >> 5);
    int c = threadIdx.x & 31;
    const float* __restrict__ Emb = g_Emb + (size_t)g * Ncfg * 32;
    float mval = g ? g_m[0][c] : g_m[1][c];
    float x = Emb[(size_t)row * 32 + c] - mval;
    __nv_bfloat16 hi = __float2bfloat16_rn(x);
    __nv_bfloat16 lo = __float2bfloat16_rn(x - __bfloat162float(hi));
    __nv_bfloat16* dst = (g ? g_Bbf : g_Abf) + (size_t)row * 96;
    dst[c] = hi;
    if (g == 0) { dst[32 + c] = lo; dst[64 + c] = hi; }
    else        { dst[32 + c] = hi; dst[64 + c] = lo; }
}

// ---------------- final: out = sigmoid(A @ B^T) via mma.sync bf16 ----------------
// 128x128 block tile, K=96; 8 warps each compute 64x32.
// SMEM rows padded to 104 bf16 (208 B = 52 words): 52*r + c mod 32 covers all
// banks for the fragment access pattern -> conflict-free without swizzle.
#define ASTRIDE 208
#define FSM_TOT (2 * 128 * ASTRIDE)  // 53248

__device__ __forceinline__ void mma_bf16(float* c, const uint32_t* a, const uint32_t* b) {
    asm volatile(
        "mma.sync.aligned.m16n8k16.row.col.f32.bf16.bf16.f32 "
        "{%0,%1,%2,%3}, {%4,%5,%6,%7}, {%8,%9}, {%0,%1,%2,%3};"
        : "+f"(c[0]), "+f"(c[1]), "+f"(c[2]), "+f"(c[3])
        : "r"(a[0]), "r"(a[1]), "r"(a[2]), "r"(a[3]), "r"(b[0]), "r"(b[1]));
}

__global__ void __launch_bounds__(256, 2) final_mma_kernel(float* __restrict__ out) {
    extern __shared__ char smem[];
    char* As = smem;
    char* Bs = smem + 128 * ASTRIDE;
    int tid = threadIdx.x;
    int row0 = blockIdx.y * 128;
    int col0 = blockIdx.x * 128;

    // Fill tiles: 128 rows x 96 bf16 (192 B = 12 uint4 per row)
    {
        const uint4* __restrict__ Asrc = (const uint4*)(g_Abf + (size_t)row0 * 96);
        const uint4* __restrict__ Bsrc = (const uint4*)(g_Bbf + (size_t)col0 * 96);
#pragma unroll
        for (int t = 0; t < 6; t++) {
            int i = t * 256 + tid;      // 0..1535
            int r = i / 12, c = i % 12;
            *(uint4*)(As + r * ASTRIDE + c * 16) = Asrc[i];
            *(uint4*)(Bs + r * ASTRIDE + c * 16) = Bsrc[i];
        }
    }
    __syncthreads();

    int wid = tid >> 5, lane = tid & 31;
    int gid = lane >> 2, tig = lane & 3;
    int wr0 = (wid >> 2) * 64;   // warp row base within tile
    int wc0 = (wid & 3) * 32;    // warp col base

    float acc[4][4][4];
#pragma unroll
    for (int mi = 0; mi < 4; mi++)
#pragma unroll
        for (int ni = 0; ni < 4; ni++)
#pragma unroll
            for (int q = 0; q < 4; q++) acc[mi][ni][q] = 0.f;

#pragma unroll
    for (int ks = 0; ks < 6; ks++) {
        int kb = ks * 32 + tig * 4;  // byte offset of this lane's k-pair
        uint32_t a[4][4], b[4][2];
#pragma unroll
        for (int mi = 0; mi < 4; mi++) {
            const char* base = As + (wr0 + mi * 16 + gid) * ASTRIDE + kb;
            a[mi][0] = *(const uint32_t*)(base);
            a[mi][1] = *(const uint32_t*)(base + 8 * ASTRIDE);
            a[mi][2] = *(const uint32_t*)(base + 16);
            a[mi][3] = *(const uint32_t*)(base + 8 * ASTRIDE + 16);
        }
#pragma unroll
        for (int ni = 0; ni < 4; ni++) {
            const char* base = Bs + (wc0 + ni * 8 + gid) * ASTRIDE + kb;
            b[ni][0] = *(const uint32_t*)(base);
            b[ni][1] = *(const uint32_t*)(base + 16);
        }
#pragma unroll
        for (int mi = 0; mi < 4; mi++)
#pragma unroll
            for (int ni = 0; ni < 4; ni++) mma_bf16(acc[mi][ni], a[mi], b[ni]);
    }

    // Epilogue: sigmoid + store
#pragma unroll
    for (int mi = 0; mi < 4; mi++) {
        int row = row0 + wr0 + mi * 16 + gid;
#pragma unroll
        for (int ni = 0; ni < 4; ni++) {
            int col = col0 + wc0 + ni * 8 + tig * 2;
            float* a4 = acc[mi][ni];
            float s0 = __fdividef(1.f, 1.f + __expf(-a4[0]));
            float s1 = __fdividef(1.f, 1.f + __expf(-a4[1]));
            float s2 = __fdividef(1.f, 1.f + __expf(-a4[2]));
            float s3 = __fdividef(1.f, 1.f + __expf(-a4[3]));
            *(float2*)&out[(size_t)row * Ncfg + col]       = make_float2(s0, s1);
            *(float2*)&out[(size_t)(row + 8) * Ncfg + col] = make_float2(s2, s3);
        }
    }
}

// ---------------- launch ----------------
extern "C" void kernel_launch(void* const* d_in, const int* in_sizes, int n_in,
                              void* d_out, int out_size) {
    (void)in_sizes; (void)n_in; (void)out_size;
    const int*   e1 = (const int*)d_in[0];
    const int*   e2 = (const int*)d_in[1];
    const float* x1 = (const float*)d_in[2];
    const float* x2 = (const float*)d_in[3];
    const float* W1 = (const float*)d_in[4];
    const float* b1 = (const float*)d_in[5];
    const float* W2 = (const float*)d_in[6];
    const float* b2 = (const float*)d_in[7];
    const float* W3 = (const float*)d_in[8];
    const float* b3 = (const float*)d_in[9];
    const float* M1 = (const float*)d_in[10];
    const float* M2 = (const float*)d_in[11];
    float* out = (float*)d_out;

    static bool attr_done = false;
    if (!attr_done) {
        cudaFuncSetAttribute(final_mma_kernel,
                             cudaFuncAttributeMaxDynamicSharedMemorySize, FSM_TOT);
        attr_done = true;
    }

    // CSR build
    zero_deg_kernel<<<16, 1024>>>();
    count_kernel<<<dim3(32, 2), 1024>>>(e1, e2);
    scan_kernel<<<2, 1024>>>();
    fill_kernel<<<dim3(Ecfg / 256, 2), 256>>>(e1, e2);

    // Layer 1: T = Agg(X);  H1 = relu(T@W1 + b1)
    agg_kernel<64, 0, true><<<dim3(Ncfg / 8, 2), 256>>>(x1, x2, 0, BUF_T, nullptr);
    gemm_kernel<64, 128, true><<<dim3(Ncfg / 16, 2), 256>>>(BUF_T, BUF_H1, W1, b1);

    // Layer 2: G2 = H1@W2;  H2 = relu(Agg(G2) + b2)
    gemm_kernel<128, 64, false><<<dim3(Ncfg / 32, 2), 256>>>(BUF_H1, BUF_G2, W2, nullptr);
    agg_kernel<64, 1, false><<<dim3(Ncfg / 8, 2), 256>>>(nullptr, nullptr, BUF_G2, BUF_H2, b2);

    // Layer 3: G3 = H2@W3;  Emb = Agg(G3) + b3
    gemm_kernel<64, 32, false><<<dim3(Ncfg / 64, 2), 256>>>(BUF_H2, BUF_G3, W3, nullptr);
    agg_kernel<32, 2, false><<<dim3(Ncfg / 8, 2), 256>>>(nullptr, nullptr, BUF_G3, BUF_EMB, b3);

    // Matching vectors
    match_partial_kernel<<<dim3(64, 2), 256>>>();
    match_final_kernel<<<1, 64>>>(M1, M2);

    // bf16-split operands + HMMA final
    prep_kernel<<<dim3(Ncfg / 8, 2), 256>>>();
    final_mma_kernel<<<dim3(Ncfg / 128, Ncfg / 128), 256, FSM_TOT>>>(out);
}

// round 5
// speedup vs baseline: 1.3632x; 1.0388x over previous
#include <cuda_runtime.h>
#include <cuda_bf16.h>
#include <cstdint>

#define Ncfg 8192
#define Ecfg 524288

// ---------------- device scratch (static; no runtime allocation) ----------------
__device__ int   g_deg[2][Ncfg];
__device__ float g_dinv[2][Ncfg];
__device__ int   g_rowptr[2][Ncfg + 1];
__device__ int   g_cursor[2][Ncfg];
__device__ int   g_col[2][Ecfg];

__device__ float g_Xs [2 * Ncfg * 64];   // dinv * X  (pre-scaled layer-1 input)
__device__ float g_T  [2 * Ncfg * 64];   // Agg(Xs)
__device__ float g_H1 [2 * Ncfg * 128];  // relu(T@W1+b1)
__device__ float g_G2 [2 * Ncfg * 64];   // dinv * (H1@W2)
__device__ float g_H2 [2 * Ncfg * 64];   // relu(Agg(G2)+b2)
__device__ float g_G3 [2 * Ncfg * 32];   // dinv * (H2@W3)
__device__ float g_Emb[2 * Ncfg * 32];   // Agg(G3)+b3
__device__ float g_m[2][32];             // matching vectors
__device__ float g_colsum[2][32];        // column sums of Emb

// bf16-split operands for the final HMMA GEMM (rows of 96 bf16):
// A row: [hi | lo | hi],  B row: [hi | hi | lo]  =>  hiA*hiB + loA*hiB + hiA*loB
__device__ __nv_bfloat16 g_Abf[(size_t)Ncfg * 96];
__device__ __nv_bfloat16 g_Bbf[(size_t)Ncfg * 96];

#define BUF_XS  0
#define BUF_T   1
#define BUF_H1  2
#define BUF_G2  3
#define BUF_H2  4
#define BUF_G3  5
#define BUF_EMB 6

__device__ __forceinline__ float* devbuf(int sel) {
    switch (sel) {
        case BUF_XS: return g_Xs;
        case BUF_T:  return g_T;
        case BUF_H1: return g_H1;
        case BUF_G2: return g_G2;
        case BUF_H2: return g_H2;
        case BUF_G3: return g_G3;
        default:     return g_Emb;
    }
}

// ---------------- CSR build ----------------
__global__ void zero_deg_kernel() {
    int i = blockIdx.x * blockDim.x + threadIdx.x;
    if (i < 2 * Ncfg) ((int*)g_deg)[i] = 0;
    if (i < 64) ((float*)g_colsum)[i] = 0.f;
}

// SMEM-privatized histogram: 32 blocks per graph
__global__ void count_kernel(const int* __restrict__ e0, const int* __restrict__ e1) {
    __shared__ int h[Ncfg];
    int g = blockIdx.y;
    const int* __restrict__ dst = (g ? e1 : e0) + Ecfg;
    for (int i = threadIdx.x; i < Ncfg; i += 1024) h[i] = 0;
    __syncthreads();
    int base = blockIdx.x * (Ecfg / 32);
#pragma unroll
    for (int t = 0; t < Ecfg / 32; t += 1024)
        atomicAdd(&h[dst[base + t + threadIdx.x]], 1);
    __syncthreads();
    for (int i = threadIdx.x; i < Ncfg; i += 1024) {
        int v = h[i];
        if (v) atomicAdd(&g_deg[g][i], v);
    }
}

__global__ void scan_kernel() {
    int g = blockIdx.x;
    int tid = threadIdx.x;
    int v[8];
    int tot = 0;
#pragma unroll
    for (int i = 0; i < 8; i++) { v[i] = g_deg[g][tid * 8 + i]; tot += v[i]; }
    __shared__ int s[1024];
    s[tid] = tot;
    __syncthreads();
    for (int off = 1; off < 1024; off <<= 1) {
        int t = (tid >= off) ? s[tid - off] : 0;
        __syncthreads();
        s[tid] += t;
        __syncthreads();
    }
    int run = s[tid] - tot;
#pragma unroll
    for (int i = 0; i < 8; i++) {
        int idx = tid * 8 + i;
        g_rowptr[g][idx] = run;
        g_cursor[g][idx] = run;
        g_dinv[g][idx] = rsqrtf((float)(v[i] + 1));
        run += v[i];
    }
    if (tid == 1023) g_rowptr[g][Ncfg] = run;
}

__global__ void fill_kernel(const int* __restrict__ e0, const int* __restrict__ e1) {
    int g = blockIdx.y;
    const int* e = g ? e1 : e0;
    int i = blockIdx.x * blockDim.x + threadIdx.x;
    if (i < Ecfg) {
        int d = e[Ecfg + i];
        int p = atomicAdd(&g_cursor[g][d], 1);
        g_col[g][p] = e[i];
    }
}

// ---------------- pre-scale layer-1 input: Xs = dinv[row] * X ----------------
__global__ void scale_x_kernel(const float* __restrict__ x1, const float* __restrict__ x2) {
    int g = blockIdx.y;
    const float* __restrict__ X = g ? x2 : x1;
    float* __restrict__ O = g_Xs + (size_t)g * Ncfg * 64;
    int i = blockIdx.x * blockDim.x + threadIdx.x;   // float4 index, 16 per row
    int row = i >> 4;
    float dv = g_dinv[g][row];
    float4 v = ((const float4*)X)[i];
    ((float4*)O)[i] = make_float4(dv * v.x, dv * v.y, dv * v.z, dv * v.w);
}

// ---------------- aggregation (inputs pre-scaled by dinv) ----------------
// out[d] = dinv[d] * ( P'[d] + sum_{s->d} P'[s] )  (+bias)(relu)
// EPI: 0 = none, 1 = bias+relu, 2 = bias
template <int F, int EPI>
__global__ void agg_kernel(int inSel, int outSel, const float* __restrict__ bias) {
    int g = blockIdx.y;
    const float* __restrict__ P = devbuf(inSel) + (size_t)g * Ncfg * F;
    float* __restrict__ O = devbuf(outSel) + (size_t)g * Ncfg * F;
    const int* __restrict__ col = g_col[g];

    int warp = (blockIdx.x * blockDim.x + threadIdx.x) >> 5;
    int lane = threadIdx.x & 31;
    if (warp >= Ncfg) return;
    int d = warp;
    int beg = g_rowptr[g][d];
    int end = g_rowptr[g][d + 1];
    float wd = g_dinv[g][d];

    if (F == 64) {
        float2 pv = ((const float2*)(P + (size_t)d * 64))[lane];
        float ax = pv.x, ay = pv.y;
        int j = beg;
        int alim = min(end, (beg + 3) & ~3);
        for (; j < alim; ++j) {
            float2 v = ((const float2*)(P + (size_t)col[j] * 64))[lane];
            ax += v.x; ay += v.y;
        }
        for (; j + 8 <= end; j += 8) {
            int4 c0 = *(const int4*)&col[j];
            int4 c1 = *(const int4*)&col[j + 4];
            float2 v0 = ((const float2*)(P + (size_t)c0.x * 64))[lane];
            float2 v1 = ((const float2*)(P + (size_t)c0.y * 64))[lane];
            float2 v2 = ((const float2*)(P + (size_t)c0.z * 64))[lane];
            float2 v3 = ((const float2*)(P + (size_t)c0.w * 64))[lane];
            float2 v4 = ((const float2*)(P + (size_t)c1.x * 64))[lane];
            float2 v5 = ((const float2*)(P + (size_t)c1.y * 64))[lane];
            float2 v6 = ((const float2*)(P + (size_t)c1.z * 64))[lane];
            float2 v7 = ((const float2*)(P + (size_t)c1.w * 64))[lane];
            ax += v0.x; ay += v0.y; ax += v1.x; ay += v1.y;
            ax += v2.x; ay += v2.y; ax += v3.x; ay += v3.y;
            ax += v4.x; ay += v4.y; ax += v5.x; ay += v5.y;
            ax += v6.x; ay += v6.y; ax += v7.x; ay += v7.y;
        }
        for (; j < end; ++j) {
            float2 v = ((const float2*)(P + (size_t)col[j] * 64))[lane];
            ax += v.x; ay += v.y;
        }
        ax *= wd; ay *= wd;
        if (EPI >= 1) {
            ax += bias[2 * lane];
            ay += bias[2 * lane + 1];
            if (EPI == 1) { ax = fmaxf(ax, 0.f); ay = fmaxf(ay, 0.f); }
        }
        ((float2*)(O + (size_t)d * 64))[lane] = make_float2(ax, ay);
    } else {  // F == 32
        float a = P[(size_t)d * 32 + lane];
        int j = beg;
        int alim = min(end, (beg + 3) & ~3);
        for (; j < alim; ++j) a += P[(size_t)col[j] * 32 + lane];
        for (; j + 8 <= end; j += 8) {
            int4 c0 = *(const int4*)&col[j];
            int4 c1 = *(const int4*)&col[j + 4];
            float v0 = P[(size_t)c0.x * 32 + lane];
            float v1 = P[(size_t)c0.y * 32 + lane];
            float v2 = P[(size_t)c0.z * 32 + lane];
            float v3 = P[(size_t)c0.w * 32 + lane];
            float v4 = P[(size_t)c1.x * 32 + lane];
            float v5 = P[(size_t)c1.y * 32 + lane];
            float v6 = P[(size_t)c1.z * 32 + lane];
            float v7 = P[(size_t)c1.w * 32 + lane];
            a += v0; a += v1; a += v2; a += v3;
            a += v4; a += v5; a += v6; a += v7;
        }
        for (; j < end; ++j) a += P[(size_t)col[j] * 32 + lane];
        a *= wd;
        if (EPI >= 1) {
            a += bias[lane];
            if (EPI == 1) a = fmaxf(a, 0.f);
        }
        O[(size_t)d * 32 + lane] = a;
    }
}

// ---------------- small dense GEMM: O = [dinv*] (X[NxK] @ W[KxNOUT]) (+bias, relu) ----------------
template <int K, int NOUT, bool BR, bool SCALE>
__global__ void gemm_kernel(int inSel, int outSel,
                            const float* __restrict__ W, const float* __restrict__ bias) {
    constexpr int CG = NOUT / 8;
    constexpr int ROWS = 256 / CG;
    int g = blockIdx.y;
    const float* __restrict__ X = devbuf(inSel) + (size_t)g * Ncfg * K;
    float* __restrict__ O = devbuf(outSel) + (size_t)g * Ncfg * NOUT;

    __shared__ float Ws[K * NOUT];
    __shared__ float Xs[ROWS * K];
    int tid = threadIdx.x;
    for (int i = tid; i < K * NOUT; i += 256) Ws[i] = W[i];
    int row0 = blockIdx.x * ROWS;
    for (int i = tid; i < ROWS * K; i += 256) Xs[i] = X[(size_t)row0 * K + i];
    __syncthreads();

    int cgi = tid % CG;
    int r = tid / CG;
    int c0 = cgi * 8;
    float acc[8];
#pragma unroll
    for (int i = 0; i < 8; i++) acc[i] = BR ? bias[c0 + i] : 0.f;

#pragma unroll 4
    for (int k = 0; k < K; k++) {
        float x = Xs[r * K + k];
        float4 w0 = *(const float4*)&Ws[k * NOUT + c0];
        float4 w1 = *(const float4*)&Ws[k * NOUT + c0 + 4];
        acc[0] += x * w0.x; acc[1] += x * w0.y; acc[2] += x * w0.z; acc[3] += x * w0.w;
        acc[4] += x * w1.x; acc[5] += x * w1.y; acc[6] += x * w1.z; acc[7] += x * w1.w;
    }
    if (BR) {
#pragma unroll
        for (int i = 0; i < 8; i++) acc[i] = fmaxf(acc[i], 0.f);
    }
    if (SCALE) {
        float dv = g_dinv[g][row0 + r];
#pragma unroll
        for (int i = 0; i < 8; i++) acc[i] *= dv;
    }
    size_t off = (size_t)(row0 + r) * NOUT + c0;
    *(float4*)&O[off]     = make_float4(acc[0], acc[1], acc[2], acc[3]);
    *(float4*)&O[off + 4] = make_float4(acc[4], acc[5], acc[6], acc[7]);
}

// ---------------- matching: colsum partials + finish ----------------
__global__ void match_partial_kernel() {
    int g = blockIdx.y;
    const float* __restrict__ Emb = g_Emb + (size_t)g * Ncfg * 32;
    int tid = threadIdx.x;
    int col = tid & 31;
    int seg = tid >> 5;
    int rbeg = blockIdx.x * 128 + seg * 16;
    float p = 0.f;
#pragma unroll
    for (int r = 0; r < 16; r++) p += Emb[(size_t)(rbeg + r) * 32 + col];
    __shared__ float red[256];
    red[tid] = p;
    __syncthreads();
    for (int st = 128; st >= 32; st >>= 1) {
        if (tid < st) red[tid] += red[tid + st];
        __syncthreads();
    }
    if (tid < 32) atomicAdd(&g_colsum[g][tid], red[tid]);
}

__global__ void match_final_kernel(const float* __restrict__ M1, const float* __restrict__ M2) {
    int tid = threadIdx.x;
    int g = tid >> 5, c = tid & 31;
    const float* __restrict__ M = g ? M2 : M1;
    float mm = 0.f;
#pragma unroll
    for (int k = 0; k < 32; k++) mm += g_colsum[g][k] * M[k * 32 + c];
    g_m[g][c] = tanhf(mm);
}

// ---------------- prep: bf16 hi/lo split operands ----------------
__global__ void prep_kernel() {
    int g = blockIdx.y;
    int row = blockIdx.x * 8 + (threadIdx.x >> 5);
    int c = threadIdx.x & 31;
    const float* __restrict__ Emb = g_Emb + (size_t)g * Ncfg * 32;
    float mval = g ? g_m[0][c] : g_m[1][c];
    float x = Emb[(size_t)row * 32 + c] - mval;
    __nv_bfloat16 hi = __float2bfloat16_rn(x);
    __nv_bfloat16 lo = __float2bfloat16_rn(x - __bfloat162float(hi));
    __nv_bfloat16* dst = (g ? g_Bbf : g_Abf) + (size_t)row * 96;
    dst[c] = hi;
    if (g == 0) { dst[32 + c] = lo; dst[64 + c] = hi; }
    else        { dst[32 + c] = hi; dst[64 + c] = lo; }
}

// ---------------- final: out = sigmoid(A @ B^T) via mma.sync bf16 ----------------
#define ASTRIDE 208
#define FSM_TOT (2 * 128 * ASTRIDE)  // 53248

__device__ __forceinline__ void mma_bf16(float* c, const uint32_t* a, const uint32_t* b) {
    asm volatile(
        "mma.sync.aligned.m16n8k16.row.col.f32.bf16.bf16.f32 "
        "{%0,%1,%2,%3}, {%4,%5,%6,%7}, {%8,%9}, {%0,%1,%2,%3};"
        : "+f"(c[0]), "+f"(c[1]), "+f"(c[2]), "+f"(c[3])
        : "r"(a[0]), "r"(a[1]), "r"(a[2]), "r"(a[3]), "r"(b[0]), "r"(b[1]));
}

__global__ void __launch_bounds__(256, 2) final_mma_kernel(float* __restrict__ out) {
    extern __shared__ char smem[];
    char* As = smem;
    char* Bs = smem + 128 * ASTRIDE;
    int tid = threadIdx.x;
    int row0 = blockIdx.y * 128;
    int col0 = blockIdx.x * 128;

    {
        const uint4* __restrict__ Asrc = (const uint4*)(g_Abf + (size_t)row0 * 96);
        const uint4* __restrict__ Bsrc = (const uint4*)(g_Bbf + (size_t)col0 * 96);
#pragma unroll
        for (int t = 0; t < 6; t++) {
            int i = t * 256 + tid;
            int r = i / 12, c = i % 12;
            *(uint4*)(As + r * ASTRIDE + c * 16) = Asrc[i];
            *(uint4*)(Bs + r * ASTRIDE + c * 16) = Bsrc[i];
        }
    }
    __syncthreads();

    int wid = tid >> 5, lane = tid & 31;
    int gid = lane >> 2, tig = lane & 3;
    int wr0 = (wid >> 2) * 64;
    int wc0 = (wid & 3) * 32;

    float acc[4][4][4];
#pragma unroll
    for (int mi = 0; mi < 4; mi++)
#pragma unroll
        for (int ni = 0; ni < 4; ni++)
#pragma unroll
            for (int q = 0; q < 4; q++) acc[mi][ni][q] = 0.f;

#pragma unroll
    for (int ks = 0; ks < 6; ks++) {
        int kb = ks * 32 + tig * 4;
        uint32_t a[4][4], b[4][2];
#pragma unroll
        for (int mi = 0; mi < 4; mi++) {
            const char* base = As + (wr0 + mi * 16 + gid) * ASTRIDE + kb;
            a[mi][0] = *(const uint32_t*)(base);
            a[mi][1] = *(const uint32_t*)(base + 8 * ASTRIDE);
            a[mi][2] = *(const uint32_t*)(base + 16);
            a[mi][3] = *(const uint32_t*)(base + 8 * ASTRIDE + 16);
        }
#pragma unroll
        for (int ni = 0; ni < 4; ni++) {
            const char* base = Bs + (wc0 + ni * 8 + gid) * ASTRIDE + kb;
            b[ni][0] = *(const uint32_t*)(base);
            b[ni][1] = *(const uint32_t*)(base + 16);
        }
#pragma unroll
        for (int mi = 0; mi < 4; mi++)
#pragma unroll
            for (int ni = 0; ni < 4; ni++) mma_bf16(acc[mi][ni], a[mi], b[ni]);
    }

#pragma unroll
    for (int mi = 0; mi < 4; mi++) {
        int row = row0 + wr0 + mi * 16 + gid;
#pragma unroll
        for (int ni = 0; ni < 4; ni++) {
            int col = col0 + wc0 + ni * 8 + tig * 2;
            float* a4 = acc[mi][ni];
            float s0 = __fdividef(1.f, 1.f + __expf(-a4[0]));
            float s1 = __fdividef(1.f, 1.f + __expf(-a4[1]));
            float s2 = __fdividef(1.f, 1.f + __expf(-a4[2]));
            float s3 = __fdividef(1.f, 1.f + __expf(-a4[3]));
            *(float2*)&out[(size_t)row * Ncfg + col]       = make_float2(s0, s1);
            *(float2*)&out[(size_t)(row + 8) * Ncfg + col] = make_float2(s2, s3);
        }
    }
}

// ---------------- launch ----------------
extern "C" void kernel_launch(void* const* d_in, const int* in_sizes, int n_in,
                              void* d_out, int out_size) {
    (void)in_sizes; (void)n_in; (void)out_size;
    const int*   e1 = (const int*)d_in[0];
    const int*   e2 = (const int*)d_in[1];
    const float* x1 = (const float*)d_in[2];
    const float* x2 = (const float*)d_in[3];
    const float* W1 = (const float*)d_in[4];
    const float* b1 = (const float*)d_in[5];
    const float* W2 = (const float*)d_in[6];
    const float* b2 = (const float*)d_in[7];
    const float* W3 = (const float*)d_in[8];
    const float* b3 = (const float*)d_in[9];
    const float* M1 = (const float*)d_in[10];
    const float* M2 = (const float*)d_in[11];
    float* out = (float*)d_out;

    static bool attr_done = false;
    if (!attr_done) {
        cudaFuncSetAttribute(final_mma_kernel,
                             cudaFuncAttributeMaxDynamicSharedMemorySize, FSM_TOT);
        attr_done = true;
    }

    // CSR build
    zero_deg_kernel<<<16, 1024>>>();
    count_kernel<<<dim3(32, 2), 1024>>>(e1, e2);
    scan_kernel<<<2, 1024>>>();
    fill_kernel<<<dim3(Ecfg / 256, 2), 256>>>(e1, e2);

    // Pre-scale layer-1 input: Xs = dinv * X
    scale_x_kernel<<<dim3(Ncfg * 16 / 256, 2), 256>>>(x1, x2);

    // Layer 1: T = Agg(Xs);  H1 = relu(T@W1 + b1)
    agg_kernel<64, 0><<<dim3(Ncfg / 8, 2), 256>>>(BUF_XS, BUF_T, nullptr);
    gemm_kernel<64, 128, true, false><<<dim3(Ncfg / 16, 2), 256>>>(BUF_T, BUF_H1, W1, b1);

    // Layer 2: G2 = dinv*(H1@W2);  H2 = relu(Agg(G2) + b2)
    gemm_kernel<128, 64, false, true><<<dim3(Ncfg / 32, 2), 256>>>(BUF_H1, BUF_G2, W2, nullptr);
    agg_kernel<64, 1><<<dim3(Ncfg / 8, 2), 256>>>(BUF_G2, BUF_H2, b2);

    // Layer 3: G3 = dinv*(H2@W3);  Emb = Agg(G3) + b3
    gemm_kernel<64, 32, false, true><<<dim3(Ncfg / 64, 2), 256>>>(BUF_H2, BUF_G3, W3, nullptr);
    agg_kernel<32, 2><<<dim3(Ncfg / 8, 2), 256>>>(BUF_G3, BUF_EMB, b3);

    // Matching vectors
    match_partial_kernel<<<dim3(64, 2), 256>>>();
    match_final_kernel<<<1, 64>>>(M1, M2);

    // bf16-split operands + HMMA final
    prep_kernel<<<dim3(Ncfg / 8, 2), 256>>>();
    final_mma_kernel<<<dim3(Ncfg / 128, Ncfg / 128), 256, FSM_TOT>>>(out);
}

// round 7
// speedup vs baseline: 1.4443x; 1.0595x over previous
#include <cuda_runtime.h>
#include <cuda_bf16.h>
#include <cstdint>

#define Ncfg 8192
#define Ecfg 524288

// ---------------- device scratch (static; no runtime allocation) ----------------
__device__ int   g_deg[2][Ncfg];
__device__ float g_dinv[2][Ncfg];
__device__ int   g_rowptr[2][Ncfg + 1];
__device__ int   g_cursor[2][Ncfg];
__device__ int   g_col[2][Ecfg];

__device__ float g_Xs [2 * Ncfg * 64];   // dinv * X
__device__ float g_T  [2 * Ncfg * 64];   // Agg(Xs)
__device__ float g_H1 [2 * Ncfg * 128];  // relu(T@W1+b1)
__device__ float g_G2 [2 * Ncfg * 64];   // dinv * (H1@W2)
__device__ float g_H2 [2 * Ncfg * 64];   // relu(Agg(G2)+b2)
__device__ float g_G3 [2 * Ncfg * 32];   // dinv * (H2@W3)
__device__ float g_Emb[2 * Ncfg * 32];   // Agg(G3)+b3
__device__ float g_m[2][32];             // matching vectors
__device__ float g_colsum[2][32];        // column sums of Emb
__device__ int   g_sbits[2];             // absmax bits of (emb - m) per matrix

// int8 split operands for the final IMMA GEMM (rows of 96 s8):
// A row: [Xh | Xh | Xl],  B row: [Yh | Yl | Yh]
// dot = 2^7*(2^7*sum(XhYh) + sum(XhYl + XlYh)) * sA * sB   (Xl*Yl dropped)
__device__ __align__(16) signed char g_Ai8[(size_t)Ncfg * 96];
__device__ __align__(16) signed char g_Bi8[(size_t)Ncfg * 96];

#define BUF_XS  0
#define BUF_T   1
#define BUF_H1  2
#define BUF_G2  3
#define BUF_H2  4
#define BUF_G3  5
#define BUF_EMB 6

__device__ __forceinline__ float* devbuf(int sel) {
    switch (sel) {
        case BUF_XS: return g_Xs;
        case BUF_T:  return g_T;
        case BUF_H1: return g_H1;
        case BUF_G2: return g_G2;
        case BUF_H2: return g_H2;
        case BUF_G3: return g_G3;
        default:     return g_Emb;
    }
}

// ---------------- CSR build ----------------
__global__ void zero_deg_kernel() {
    int i = blockIdx.x * blockDim.x + threadIdx.x;
    if (i < 2 * Ncfg) ((int*)g_deg)[i] = 0;
    if (i < 64) ((float*)g_colsum)[i] = 0.f;
    if (i < 2) g_sbits[i] = 0;
}

__global__ void count_kernel(const int* __restrict__ e0, const int* __restrict__ e1) {
    __shared__ int h[Ncfg];
    int g = blockIdx.y;
    const int* __restrict__ dst = (g ? e1 : e0) + Ecfg;
    for (int i = threadIdx.x; i < Ncfg; i += 1024) h[i] = 0;
    __syncthreads();
    int base = blockIdx.x * (Ecfg / 32);
#pragma unroll
    for (int t = 0; t < Ecfg / 32; t += 1024)
        atomicAdd(&h[dst[base + t + threadIdx.x]], 1);
    __syncthreads();
    for (int i = threadIdx.x; i < Ncfg; i += 1024) {
        int v = h[i];
        if (v) atomicAdd(&g_deg[g][i], v);
    }
}

__global__ void scan_kernel() {
    int g = blockIdx.x;
    int tid = threadIdx.x;
    int v[8];
    int tot = 0;
#pragma unroll
    for (int i = 0; i < 8; i++) { v[i] = g_deg[g][tid * 8 + i]; tot += v[i]; }
    __shared__ int s[1024];
    s[tid] = tot;
    __syncthreads();
    for (int off = 1; off < 1024; off <<= 1) {
        int t = (tid >= off) ? s[tid - off] : 0;
        __syncthreads();
        s[tid] += t;
        __syncthreads();
    }
    int run = s[tid] - tot;
#pragma unroll
    for (int i = 0; i < 8; i++) {
        int idx = tid * 8 + i;
        g_rowptr[g][idx] = run;
        g_cursor[g][idx] = run;
        g_dinv[g][idx] = rsqrtf((float)(v[i] + 1));
        run += v[i];
    }
    if (tid == 1023) g_rowptr[g][Ncfg] = run;
}

__global__ void fill_kernel(const int* __restrict__ e0, const int* __restrict__ e1) {
    int g = blockIdx.y;
    const int* e = g ? e1 : e0;
    int i = blockIdx.x * blockDim.x + threadIdx.x;
    if (i < Ecfg) {
        int d = e[Ecfg + i];
        int p = atomicAdd(&g_cursor[g][d], 1);
        g_col[g][p] = e[i];
    }
}

// ---------------- pre-scale layer-1 input: Xs = dinv[row] * X ----------------
__global__ void scale_x_kernel(const float* __restrict__ x1, const float* __restrict__ x2) {
    int g = blockIdx.y;
    const float* __restrict__ X = g ? x2 : x1;
    float* __restrict__ O = g_Xs + (size_t)g * Ncfg * 64;
    int i = blockIdx.x * blockDim.x + threadIdx.x;
    int row = i >> 4;
    float dv = g_dinv[g][row];
    float4 v = ((const float4*)X)[i];
    ((float4*)O)[i] = make_float4(dv * v.x, dv * v.y, dv * v.z, dv * v.w);
}

// ---------------- aggregation (inputs pre-scaled by dinv) ----------------
template <int F, int EPI>
__global__ void agg_kernel(int inSel, int outSel, const float* __restrict__ bias) {
    int g = blockIdx.y;
    const float* __restrict__ P = devbuf(inSel) + (size_t)g * Ncfg * F;
    float* __restrict__ O = devbuf(outSel) + (size_t)g * Ncfg * F;
    const int* __restrict__ col = g_col[g];

    int warp = (blockIdx.x * blockDim.x + threadIdx.x) >> 5;
    int lane = threadIdx.x & 31;
    if (warp >= Ncfg) return;
    int d = warp;
    int beg = g_rowptr[g][d];
    int end = g_rowptr[g][d + 1];
    float wd = g_dinv[g][d];

    if (F == 64) {
        float2 pv = ((const float2*)(P + (size_t)d * 64))[lane];
        float ax = pv.x, ay = pv.y;
        int j = beg;
        int alim = min(end, (beg + 3) & ~3);
        for (; j < alim; ++j) {
            float2 v = ((const float2*)(P + (size_t)col[j] * 64))[lane];
            ax += v.x; ay += v.y;
        }
        for (; j + 8 <= end; j += 8) {
            int4 c0 = *(const int4*)&col[j];
            int4 c1 = *(const int4*)&col[j + 4];
            float2 v0 = ((const float2*)(P + (size_t)c0.x * 64))[lane];
            float2 v1 = ((const float2*)(P + (size_t)c0.y * 64))[lane];
            float2 v2 = ((const float2*)(P + (size_t)c0.z * 64))[lane];
            float2 v3 = ((const float2*)(P + (size_t)c0.w * 64))[lane];
            float2 v4 = ((const float2*)(P + (size_t)c1.x * 64))[lane];
            float2 v5 = ((const float2*)(P + (size_t)c1.y * 64))[lane];
            float2 v6 = ((const float2*)(P + (size_t)c1.z * 64))[lane];
            float2 v7 = ((const float2*)(P + (size_t)c1.w * 64))[lane];
            ax += v0.x; ay += v0.y; ax += v1.x; ay += v1.y;
            ax += v2.x; ay += v2.y; ax += v3.x; ay += v3.y;
            ax += v4.x; ay += v4.y; ax += v5.x; ay += v5.y;
            ax += v6.x; ay += v6.y; ax += v7.x; ay += v7.y;
        }
        for (; j < end; ++j) {
            float2 v = ((const float2*)(P + (size_t)col[j] * 64))[lane];
            ax += v.x; ay += v.y;
        }
        ax *= wd; ay *= wd;
        if (EPI >= 1) {
            ax += bias[2 * lane];
            ay += bias[2 * lane + 1];
            if (EPI == 1) { ax = fmaxf(ax, 0.f); ay = fmaxf(ay, 0.f); }
        }
        ((float2*)(O + (size_t)d * 64))[lane] = make_float2(ax, ay);
    } else {  // F == 32
        float a = P[(size_t)d * 32 + lane];
        int j = beg;
        int alim = min(end, (beg + 3) & ~3);
        for (; j < alim; ++j) a += P[(size_t)col[j] * 32 + lane];
        for (; j + 8 <= end; j += 8) {
            int4 c0 = *(const int4*)&col[j];
            int4 c1 = *(const int4*)&col[j + 4];
            float v0 = P[(size_t)c0.x * 32 + lane];
            float v1 = P[(size_t)c0.y * 32 + lane];
            float v2 = P[(size_t)c0.z * 32 + lane];
            float v3 = P[(size_t)c0.w * 32 + lane];
            float v4 = P[(size_t)c1.x * 32 + lane];
            float v5 = P[(size_t)c1.y * 32 + lane];
            float v6 = P[(size_t)c1.z * 32 + lane];
            float v7 = P[(size_t)c1.w * 32 + lane];
            a += v0; a += v1; a += v2; a += v3;
            a += v4; a += v5; a += v6; a += v7;
        }
        for (; j < end; ++j) a += P[(size_t)col[j] * 32 + lane];
        a *= wd;
        if (EPI >= 1) {
            a += bias[lane];
            if (EPI == 1) a = fmaxf(a, 0.f);
        }
        O[(size_t)d * 32 + lane] = a;
    }
}

// ---------------- small dense GEMM ----------------
template <int K, int NOUT, bool BR, bool SCALE>
__global__ void gemm_kernel(int inSel, int outSel,
                            const float* __restrict__ W, const float* __restrict__ bias) {
    constexpr int CG = NOUT / 8;
    constexpr int ROWS = 256 / CG;
    int g = blockIdx.y;
    const float* __restrict__ X = devbuf(inSel) + (size_t)g * Ncfg * K;
    float* __restrict__ O = devbuf(outSel) + (size_t)g * Ncfg * NOUT;

    __shared__ float Ws[K * NOUT];
    __shared__ float Xs[ROWS * K];
    int tid = threadIdx.x;
    for (int i = tid; i < K * NOUT; i += 256) Ws[i] = W[i];
    int row0 = blockIdx.x * ROWS;
    for (int i = tid; i < ROWS * K; i += 256) Xs[i] = X[(size_t)row0 * K + i];
    __syncthreads();

    int cgi = tid % CG;
    int r = tid / CG;
    int c0 = cgi * 8;
    float acc[8];
#pragma unroll
    for (int i = 0; i < 8; i++) acc[i] = BR ? bias[c0 + i] : 0.f;

#pragma unroll 4
    for (int k = 0; k < K; k++) {
        float x = Xs[r * K + k];
        float4 w0 = *(const float4*)&Ws[k * NOUT + c0];
        float4 w1 = *(const float4*)&Ws[k * NOUT + c0 + 4];
        acc[0] += x * w0.x; acc[1] += x * w0.y; acc[2] += x * w0.z; acc[3] += x * w0.w;
        acc[4] += x * w1.x; acc[5] += x * w1.y; acc[6] += x * w1.z; acc[7] += x * w1.w;
    }
    if (BR) {
#pragma unroll
        for (int i = 0; i < 8; i++) acc[i] = fmaxf(acc[i], 0.f);
    }
    if (SCALE) {
        float dv = g_dinv[g][row0 + r];
#pragma unroll
        for (int i = 0; i < 8; i++) acc[i] *= dv;
    }
    size_t off = (size_t)(row0 + r) * NOUT + c0;
    *(float4*)&O[off]     = make_float4(acc[0], acc[1], acc[2], acc[3]);
    *(float4*)&O[off + 4] = make_float4(acc[4], acc[5], acc[6], acc[7]);
}

// ---------------- matching: colsum partials + finish ----------------
__global__ void match_partial_kernel() {
    int g = blockIdx.y;
    const float* __restrict__ Emb = g_Emb + (size_t)g * Ncfg * 32;
    int tid = threadIdx.x;
    int col = tid & 31;
    int seg = tid >> 5;
    int rbeg = blockIdx.x * 128 + seg * 16;
    float p = 0.f;
#pragma unroll
    for (int r = 0; r < 16; r++) p += Emb[(size_t)(rbeg + r) * 32 + col];
    __shared__ float red[256];
    red[tid] = p;
    __syncthreads();
    for (int st = 128; st >= 32; st >>= 1) {
        if (tid < st) red[tid] += red[tid + st];
        __syncthreads();
    }
    if (tid < 32) atomicAdd(&g_colsum[g][tid], red[tid]);
}

__global__ void match_final_kernel(const float* __restrict__ M1, const float* __restrict__ M2) {
    int tid = threadIdx.x;
    int g = tid >> 5, c = tid & 31;
    const float* __restrict__ M = g ? M2 : M1;
    float mm = 0.f;
#pragma unroll
    for (int k = 0; k < 32; k++) mm += g_colsum[g][k] * M[k * 32 + c];
    g_m[g][c] = tanhf(mm);
}

// ---------------- absmax of (emb - m) per matrix ----------------
__global__ void amax_kernel() {
    int g = blockIdx.y;
    const float* __restrict__ Emb = g_Emb + (size_t)g * Ncfg * 32;
    int tid = threadIdx.x;
    int col = tid & 31;
    int seg = tid >> 5;
    float mval = g ? g_m[0][col] : g_m[1][col];
    int rbeg = blockIdx.x * 128 + seg * 16;
    float v = 0.f;
#pragma unroll
    for (int r = 0; r < 16; r++)
        v = fmaxf(v, fabsf(Emb[(size_t)(rbeg + r) * 32 + col] - mval));
#pragma unroll
    for (int off = 16; off >= 1; off >>= 1)
        v = fmaxf(v, __shfl_xor_sync(0xffffffffu, v, off));
    __shared__ float wmax[8];
    if (col == 0) wmax[seg] = v;
    __syncthreads();
    if (tid == 0) {
        float m = wmax[0];
#pragma unroll
        for (int i = 1; i < 8; i++) m = fmaxf(m, wmax[i]);
        atomicMax(&g_sbits[g], __float_as_int(m));
    }
}

// ---------------- prep: int8 split operands ----------------
__global__ void prep_i8_kernel() {
    int g = blockIdx.y;
    int row = blockIdx.x * 8 + (threadIdx.x >> 5);
    int c = threadIdx.x & 31;
    const float* __restrict__ Emb = g_Emb + (size_t)g * Ncfg * 32;
    float mval = g ? g_m[0][c] : g_m[1][c];
    float sstep = __int_as_float(g_sbits[g]) * (1.f / 16256.f);
    float inv = (sstep > 0.f) ? __fdividef(1.f, sstep) : 0.f;
    float x = Emb[(size_t)row * 32 + c] - mval;
    int X = __float2int_rn(x * inv);
    X = max(-16256, min(16256, X));
    int Xh = (X + 64) >> 7;          // round-to-nearest(X/128), Xh in [-127,127]
    int Xl = X - (Xh << 7);          // Xl in [-64, 63]
    signed char* dst = (g ? g_Bi8 : g_Ai8) + (size_t)row * 96;
    dst[c] = (signed char)Xh;
    if (g == 0) { dst[32 + c] = (signed char)Xh; dst[64 + c] = (signed char)Xl; }
    else        { dst[32 + c] = (signed char)Xl; dst[64 + c] = (signed char)Xh; }
}

// ---------------- final: out = sigmoid(A @ B^T) via mma.sync s8 ----------------
// 128x128 tile, 8 warps of 64x32. Phase 1: Xh*Yh (K=32); acc <<= 7;
// Phase 2: Xh*Yl + Xl*Yh (K=64). result = acc * 128 * sA * sB.
#define ISTRIDE 112  // 96-byte rows padded to 112 -> conflict-free frag LDS

__device__ __forceinline__ void mma_s8(int* c, const uint32_t* a, const uint32_t* b) {
    asm volatile(
        "mma.sync.aligned.m16n8k32.row.col.s32.s8.s8.s32 "
        "{%0,%1,%2,%3}, {%4,%5,%6,%7}, {%8,%9}, {%0,%1,%2,%3};"
        : "+r"(c[0]), "+r"(c[1]), "+r"(c[2]), "+r"(c[3])
        : "r"(a[0]), "r"(a[1]), "r"(a[2]), "r"(a[3]), "r"(b[0]), "r"(b[1]));
}

__global__ void __launch_bounds__(256, 2) final_imma_kernel(float* __restrict__ out) {
    __shared__ char As[128 * ISTRIDE];
    __shared__ char Bs[128 * ISTRIDE];
    int tid = threadIdx.x;
    int row0 = blockIdx.y * 128;
    int col0 = blockIdx.x * 128;

    {
        const uint4* __restrict__ Asrc = (const uint4*)(g_Ai8 + (size_t)row0 * 96);
        const uint4* __restrict__ Bsrc = (const uint4*)(g_Bi8 + (size_t)col0 * 96);
#pragma unroll
        for (int t = 0; t < 3; t++) {
            int i = t * 256 + tid;        // 0..767, 6 uint4 per 96B row
            int r = i / 6, c = i % 6;
            *(uint4*)(As + r * ISTRIDE + c * 16) = Asrc[i];
            *(uint4*)(Bs + r * ISTRIDE + c * 16) = Bsrc[i];
        }
    }
    __syncthreads();

    int wid = tid >> 5, lane = tid & 31;
    int gid = lane >> 2, tig = lane & 3;
    int wr0 = (wid >> 2) * 64;
    int wc0 = (wid & 3) * 32;

    int acc[4][4][4];
#pragma unroll
    for (int mi = 0; mi < 4; mi++)
#pragma unroll
        for (int ni = 0; ni < 4; ni++)
#pragma unroll
            for (int q = 0; q < 4; q++) acc[mi][ni][q] = 0;

#pragma unroll
    for (int ks = 0; ks < 3; ks++) {
        int kb = ks * 32 + tig * 4;
        uint32_t a[4][4], b[4][2];
#pragma unroll
        for (int mi = 0; mi < 4; mi++) {
            const char* base = As + (wr0 + mi * 16 + gid) * ISTRIDE + kb;
            a[mi][0] = *(const uint32_t*)(base);
            a[mi][1] = *(const uint32_t*)(base + 8 * ISTRIDE);
            a[mi][2] = *(const uint32_t*)(base + 16);
            a[mi][3] = *(const uint32_t*)(base + 8 * ISTRIDE + 16);
        }
#pragma unroll
        for (int ni = 0; ni < 4; ni++) {
            const char* base = Bs + (wc0 + ni * 8 + gid) * ISTRIDE + kb;
            b[ni][0] = *(const uint32_t*)(base);
            b[ni][1] = *(const uint32_t*)(base + 16);
        }
#pragma unroll
        for (int mi = 0; mi < 4; mi++)
#pragma unroll
            for (int ni = 0; ni < 4; ni++) mma_s8(acc[mi][ni], a[mi], b[ni]);

        if (ks == 0) {
            // weight the Xh*Yh phase by 2^7 before the mixed phase accumulates
#pragma unroll
            for (int mi = 0; mi < 4; mi++)
#pragma unroll
                for (int ni = 0; ni < 4; ni++)
#pragma unroll
                    for (int q = 0; q < 4; q++) acc[mi][ni][q] <<= 7;
        }
    }

    float sa = __int_as_float(g_sbits[0]) * (1.f / 16256.f);
    float sb = __int_as_float(g_sbits[1]) * (1.f / 16256.f);
    float sc = sa * sb * 128.f;

#pragma unroll
    for (int mi = 0; mi < 4; mi++) {
        int row = row0 + wr0 + mi * 16 + gid;
#pragma unroll
        for (int ni = 0; ni < 4; ni++) {
            int col = col0 + wc0 + ni * 8 + tig * 2;
            int* a4 = acc[mi][ni];
            float f0 = (float)a4[0] * sc;
            float f1 = (float)a4[1] * sc;
            float f2 = (float)a4[2] * sc;
            float f3 = (float)a4[3] * sc;
            float s0 = __fdividef(1.f, 1.f + __expf(-f0));
            float s1 = __fdividef(1.f, 1.f + __expf(-f1));
            float s2 = __fdividef(1.f, 1.f + __expf(-f2));
            float s3 = __fdividef(1.f, 1.f + __expf(-f3));
            *(float2*)&out[(size_t)row * Ncfg + col]       = make_float2(s0, s1);
            *(float2*)&out[(size_t)(row + 8) * Ncfg + col] = make_float2(s2, s3);
        }
    }
}

// ---------------- launch ----------------
extern "C" void kernel_launch(void* const* d_in, const int* in_sizes, int n_in,
                              void* d_out, int out_size) {
    (void)in_sizes; (void)n_in; (void)out_size;
    const int*   e1 = (const int*)d_in[0];
    const int*   e2 = (const int*)d_in[1];
    const float* x1 = (const float*)d_in[2];
    const float* x2 = (const float*)d_in[3];
    const float* W1 = (const float*)d_in[4];
    const float* b1 = (const float*)d_in[5];
    const float* W2 = (const float*)d_in[6];
    const float* b2 = (const float*)d_in[7];
    const float* W3 = (const float*)d_in[8];
    const float* b3 = (const float*)d_in[9];
    const float* M1 = (const float*)d_in[10];
    const float* M2 = (const float*)d_in[11];
    float* out = (float*)d_out;

    // CSR build
    zero_deg_kernel<<<16, 1024>>>();
    count_kernel<<<dim3(32, 2), 1024>>>(e1, e2);
    scan_kernel<<<2, 1024>>>();
    fill_kernel<<<dim3(Ecfg / 256, 2), 256>>>(e1, e2);

    // Pre-scale layer-1 input
    scale_x_kernel<<<dim3(Ncfg * 16 / 256, 2), 256>>>(x1, x2);

    // Layer 1
    agg_kernel<64, 0><<<dim3(Ncfg / 8, 2), 256>>>(BUF_XS, BUF_T, nullptr);
    gemm_kernel<64, 128, true, false><<<dim3(Ncfg / 16, 2), 256>>>(BUF_T, BUF_H1, W1, b1);

    // Layer 2
    gemm_kernel<128, 64, false, true><<<dim3(Ncfg / 32, 2), 256>>>(BUF_H1, BUF_G2, W2, nullptr);
    agg_kernel<64, 1><<<dim3(Ncfg / 8, 2), 256>>>(BUF_G2, BUF_H2, b2);

    // Layer 3
    gemm_kernel<64, 32, false, true><<<dim3(Ncfg / 64, 2), 256>>>(BUF_H2, BUF_G3, W3, nullptr);
    agg_kernel<32, 2><<<dim3(Ncfg / 8, 2), 256>>>(BUF_G3, BUF_EMB, b3);

    // Matching vectors + quantization scales
    match_partial_kernel<<<dim3(64, 2), 256>>>();
    match_final_kernel<<<1, 64>>>(M1, M2);
    amax_kernel<<<dim3(64, 2), 256>>>();

    // int8 split operands + IMMA final
    prep_i8_kernel<<<dim3(Ncfg / 8, 2), 256>>>();
    final_imma_kernel<<<dim3(Ncfg / 128, Ncfg / 128), 256>>>(out);
}